// round 11
// baseline (speedup 1.0000x reference)
#include <cuda_runtime.h>
#include <cuda_fp16.h>
#include <cstdint>

// R11: two-kernel flash attention, single-term fp16 K (K_lo dropped: score
// error rms ~1.4e-4, harmless). K1 converts K,V fp32->fp16 once per
// (b,h,64-key tile) into device scratch (smem layout, swizzled, 16KB/tile).
// K2: cp.async double-buffered FA2 mma.sync, 4 warps x 32 q-rows, Q overlay
// in BUF1, exp2 softmax with mask folded into bias, mean(V) for L==0.

#define S_LEN 1024
#define BQ 128
#define BK 64
#define THREADS 128
#define LOG2E 1.44269504f
#define C2 13.0f

// smem (36KB): BUF0 [0,16K), BUF1 [16K,32K), bias [32K,36K)
// Q staging overlays BUF1 (dead after qf hoist).
#define BUF0    0u
#define BUF1    16384u
#define OFF_Q   16384u
#define KHI     0u
#define VHI     8192u
#define OFF_BIAS 32768u
#define SMEM_TOTAL 36864

#define TILE_BYTES 16384
// [b][h][t] -> 16KB tile: [K 8K][V 8K], swizzled like smem
__device__ __align__(16) unsigned char g_kv[8 * 16 * 16 * TILE_BYTES];

static __device__ __forceinline__ uint32_t smem_u32(const void* p) {
    uint32_t a;
    asm("{ .reg .u64 t; cvta.to.shared.u64 t, %1; cvt.u32.u64 %0, t; }" : "=r"(a) : "l"(p));
    return a;
}
static __device__ __forceinline__ void ldsm4(uint32_t addr, uint32_t& r0, uint32_t& r1,
                                             uint32_t& r2, uint32_t& r3) {
    asm volatile("ldmatrix.sync.aligned.m8n8.x4.shared.b16 {%0,%1,%2,%3}, [%4];"
                 : "=r"(r0), "=r"(r1), "=r"(r2), "=r"(r3) : "r"(addr));
}
static __device__ __forceinline__ void ldsm4t(uint32_t addr, uint32_t& r0, uint32_t& r1,
                                              uint32_t& r2, uint32_t& r3) {
    asm volatile("ldmatrix.sync.aligned.m8n8.x4.trans.shared.b16 {%0,%1,%2,%3}, [%4];"
                 : "=r"(r0), "=r"(r1), "=r"(r2), "=r"(r3) : "r"(addr));
}
static __device__ __forceinline__ void mma16816(float* c, uint32_t a0, uint32_t a1,
                                                uint32_t a2, uint32_t a3,
                                                uint32_t b0, uint32_t b1) {
    asm volatile("mma.sync.aligned.m16n8k16.row.col.f32.f16.f16.f32 "
                 "{%0,%1,%2,%3}, {%4,%5,%6,%7}, {%8,%9}, {%0,%1,%2,%3};"
                 : "+f"(c[0]), "+f"(c[1]), "+f"(c[2]), "+f"(c[3])
                 : "r"(a0), "r"(a1), "r"(a2), "r"(a3), "r"(b0), "r"(b1));
}
static __device__ __forceinline__ uint32_t pack_f16(float x, float y) {
    uint32_t r;
    asm("cvt.rn.f16x2.f32 %0, %1, %2;" : "=r"(r) : "f"(y), "f"(x));  // x->lo, y->hi
    return r;
}
static __device__ __forceinline__ void cp16(uint32_t daddr, const void* gaddr) {
    asm volatile("cp.async.cg.shared.global [%0], [%1], 16;" :: "r"(daddr), "l"(gaddr));
}
static __device__ __forceinline__ void cp_commit() {
    asm volatile("cp.async.commit_group;");
}
template <int N> static __device__ __forceinline__ void cp_wait() {
    asm volatile("cp.async.wait_group %0;" :: "n"(N) : "memory");
}

// ---------------- kernel 1: convert K/V to fp16 tiles ----------------
__global__ void __launch_bounds__(128)
convert_kv(const float* __restrict__ mem, const int* __restrict__ seqlen)
{
    const int t = blockIdx.x, h = blockIdx.y, b = blockIdx.z;
    const int L = seqlen[b];
    if (L == 0 || t * BK >= L) return;
    const int tid = threadIdx.x;

    const float* kb = mem + (size_t)b * S_LEN * 2048 + h * 64;
    const float* vb = kb + 1024;
    unsigned char* dst = g_kv + ((size_t)((b * 16 + h) * 16 + t)) * TILE_BYTES;

    #pragma unroll
    for (int i = 0; i < 8; i++) {
        int idx = tid + i * 128, row = idx >> 4, c4 = idx & 15;
        uint32_t off = (uint32_t)(row * 128 + (((c4 >> 1) ^ (row & 7)) << 4) + ((c4 & 1) << 3));
        float4 kv = *reinterpret_cast<const float4*>(kb + (size_t)(t * BK + row) * 2048 + c4 * 4);
        uint2 hk = { pack_f16(kv.x, kv.y), pack_f16(kv.z, kv.w) };
        *reinterpret_cast<uint2*>(dst + KHI + off) = hk;
        float4 vv = *reinterpret_cast<const float4*>(vb + (size_t)(t * BK + row) * 2048 + c4 * 4);
        uint2 hv = { pack_f16(vv.x, vv.y), pack_f16(vv.z, vv.w) };
        *reinterpret_cast<uint2*>(dst + VHI + off) = hv;
    }
}

// ---------------- kernel 2: attention ----------------
__global__ void __launch_bounds__(THREADS, 3)
attn_mma_kernel(const float* __restrict__ mem, const float* __restrict__ qry,
                const float* __restrict__ bias, const int* __restrict__ seqlen,
                float* __restrict__ out)
{
    extern __shared__ char smem[];
    const uint32_t sb = smem_u32(smem);
    const int tid = threadIdx.x, lane = tid & 31, wid = tid >> 5;   // 4 warps
    const int qt = blockIdx.x, h = blockIdx.y, b = blockIdx.z;

    const int L = seqlen[b];
    float* obase0 = out + ((size_t)(b * S_LEN + qt * BQ)) * 1024 + h * 64;

    if (L == 0) {
        // softmax exactly uniform (fp32 rounding of -1e12): O = mean_k V
        const float* vbase = mem + (size_t)b * S_LEN * 2048 + 1024 + h * 64;
        float* red = reinterpret_cast<float*>(smem);
        int d = tid & 63, slc = tid >> 6;
        float s = 0.f;
        #pragma unroll 4
        for (int k = slc * 512; k < slc * 512 + 512; k++)
            s += vbase[(size_t)k * 2048 + d];
        red[slc * 64 + d] = s;
        __syncthreads();
        if (tid < 64) red[128 + tid] = (red[tid] + red[64 + tid]) * (1.f / 1024.f);
        __syncthreads();
        #pragma unroll
        for (int r = 0; r < 16; r++) {
            int idx = tid + r * THREADS;
            int row = idx >> 4, c4 = idx & 15;
            float4 vv = *reinterpret_cast<const float4*>(&red[128 + c4 * 4]);
            *reinterpret_cast<float4*>(obase0 + (size_t)row * 1024 + c4 * 4) = vv;
        }
        return;
    }

    const int nt = (L + BK - 1) >> 6;
    const unsigned char* kvbase = g_kv + ((size_t)((b * 16 + h) * 16)) * TILE_BYTES;

    // start tile-0 transfer ASAP (BUF0; Q staging lives in BUF1)
    {
        #pragma unroll
        for (int i = 0; i < 8; i++) {
            int c = tid + i * THREADS;
            cp16(sb + BUF0 + (uint32_t)c * 16, kvbase + (size_t)c * 16);
        }
        cp_commit();
    }

    float* Bs = reinterpret_cast<float*>(smem + OFF_BIAS);
    #pragma unroll
    for (int i = tid; i < S_LEN; i += THREADS)
        Bs[i] = (i < L) ? bias[i] * LOG2E - C2 : -1e30f;

    // Q tile [128 x 64] scaled by (1/8)*log2e, fp16, swizzled -> overlay in BUF1
    const float* qbase = qry + ((size_t)(b * S_LEN + qt * BQ)) * 1024 + h * 64;
    #pragma unroll
    for (int r = 0; r < 16; r++) {
        int idx = tid + r * THREADS;
        int row = idx >> 4, c4 = idx & 15;
        float4 v = *reinterpret_cast<const float4*>(qbase + (size_t)row * 1024 + c4 * 4);
        const float sc = 0.125f * LOG2E;
        uint32_t off = (uint32_t)(row * 128 + (((c4 >> 1) ^ (row & 7)) << 4) + ((c4 & 1) << 3));
        uint2 q16 = { pack_f16(v.x * sc, v.y * sc), pack_f16(v.z * sc, v.w * sc) };
        *reinterpret_cast<uint2*>(smem + OFF_Q + off) = q16;
    }
    __syncthreads();   // Q visible to all warps

    // lane geometry
    const int s7 = lane & 7;
    const int qA = (lane & 7) + ((lane >> 3) & 1) * 8;
    const int qB = lane >> 4;
    const int kA = (lane & 7) + (lane >> 4) * 8;
    const int kB = (lane >> 3) & 1;

    // hoist Q fragments across the whole key loop (Q smem dead afterwards)
    uint32_t qf[4][2][4];
    #pragma unroll
    for (int kk = 0; kk < 4; kk++)
        #pragma unroll
        for (int rb = 0; rb < 2; rb++)
            ldsm4(sb + OFF_Q + (uint32_t)((32 * wid + 16 * rb + qA) * 128 +
                  (((2 * kk + qB) ^ s7) << 4)),
                  qf[kk][rb][0], qf[kk][rb][1], qf[kk][rb][2], qf[kk][rb][3]);
    __syncthreads();   // all qf loaded before BUF1 is overwritten

    float oacc[2][8][4];
    #pragma unroll
    for (int rb = 0; rb < 2; rb++)
        #pragma unroll
        for (int i = 0; i < 8; i++)
            #pragma unroll
            for (int j = 0; j < 4; j++) oacc[rb][i][j] = 0.f;
    float lsA[2] = {0.f, 0.f}, lsB[2] = {0.f, 0.f};

    for (int t = 0; t < nt; t++) {
        const int s0 = t * BK;
        const uint32_t kb = sb + ((t & 1) ? BUF1 : BUF0);

        if (t + 1 < nt) {   // issue next tile into the other buffer
            const unsigned char* src = kvbase + (size_t)(t + 1) * TILE_BYTES;
            const uint32_t db = ((t + 1) & 1) ? BUF1 : BUF0;
            #pragma unroll
            for (int i = 0; i < 8; i++) {
                int c = tid + i * THREADS;
                cp16(sb + db + (uint32_t)c * 16, src + (size_t)c * 16);
            }
            cp_commit();
            cp_wait<1>();   // tile t complete
        } else {
            cp_wait<0>();
        }
        __syncthreads();

        #pragma unroll
        for (int jj = 0; jj < 4; jj++) {          // 16-key group
            float sacc[2][2][4];
            #pragma unroll
            for (int rb = 0; rb < 2; rb++)
                #pragma unroll
                for (int u = 0; u < 2; u++)
                    #pragma unroll
                    for (int j = 0; j < 4; j++) sacc[rb][u][j] = 0.f;

            // ---- S = Q * K (single fp16 term) ----
            #pragma unroll
            for (int kk = 0; kk < 4; kk++) {
                uint32_t kh0, kh1, kh2, kh3;
                uint32_t ak = kb + KHI + (uint32_t)((16 * jj + kA) * 128 +
                              (((2 * kk + kB) ^ s7) << 4));
                ldsm4(ak, kh0, kh1, kh2, kh3);
                #pragma unroll
                for (int rb = 0; rb < 2; rb++) {
                    mma16816(sacc[rb][0], qf[kk][rb][0], qf[kk][rb][1], qf[kk][rb][2], qf[kk][rb][3], kh0, kh1);
                    mma16816(sacc[rb][1], qf[kk][rb][0], qf[kk][rb][1], qf[kk][rb][2], qf[kk][rb][3], kh2, kh3);
                }
            }

            uint32_t pa[2][4];
            #pragma unroll
            for (int u = 0; u < 2; u++) {
                int keyb = s0 + 16 * jj + 8 * u + 2 * (lane & 3);
                float2 bb = *reinterpret_cast<const float2*>(&Bs[keyb]);
                #pragma unroll
                for (int rb = 0; rb < 2; rb++) {
                    float p0 = exp2f(sacc[rb][u][0] + bb.x);
                    float p1 = exp2f(sacc[rb][u][1] + bb.y);
                    float p2 = exp2f(sacc[rb][u][2] + bb.x);
                    float p3 = exp2f(sacc[rb][u][3] + bb.y);
                    lsA[rb] += p0 + p1;
                    lsB[rb] += p2 + p3;
                    pa[rb][2 * u]     = pack_f16(p0, p1);
                    pa[rb][2 * u + 1] = pack_f16(p2, p3);
                }
            }

            // ---- O += P * V ----
            #pragma unroll
            for (int jn = 0; jn < 4; jn++) {
                uint32_t vh0, vh1, vh2, vh3;
                uint32_t av = kb + VHI + (uint32_t)((16 * jj + qA) * 128 +
                              (((2 * jn + qB) ^ s7) << 4));
                ldsm4t(av, vh0, vh1, vh2, vh3);
                #pragma unroll
                for (int rb = 0; rb < 2; rb++) {
                    mma16816(oacc[rb][2 * jn],     pa[rb][0], pa[rb][1], pa[rb][2], pa[rb][3], vh0, vh1);
                    mma16816(oacc[rb][2 * jn + 1], pa[rb][0], pa[rb][1], pa[rb][2], pa[rb][3], vh2, vh3);
                }
            }
        }
        __syncthreads();   // all warps done with this buffer before refill
    }

    // normalize within quads, store (each warp: rows 32*wid .. +31)
    #pragma unroll
    for (int rb = 0; rb < 2; rb++) {
        float a = lsA[rb], c = lsB[rb];
        a += __shfl_xor_sync(0xffffffffu, a, 1);
        a += __shfl_xor_sync(0xffffffffu, a, 2);
        c += __shfl_xor_sync(0xffffffffu, c, 1);
        c += __shfl_xor_sync(0xffffffffu, c, 2);
        float invA = 1.f / a, invB = 1.f / c;
        const int r = lane >> 2, c2 = (lane & 3) * 2;
        float* ob = obase0 + (size_t)(32 * wid + 16 * rb + r) * 1024;
        #pragma unroll
        for (int jd = 0; jd < 8; jd++) {
            float2 s0v = { oacc[rb][jd][0] * invA, oacc[rb][jd][1] * invA };
            float2 s1v = { oacc[rb][jd][2] * invB, oacc[rb][jd][3] * invB };
            *reinterpret_cast<float2*>(ob + 8 * jd + c2) = s0v;
            *reinterpret_cast<float2*>(ob + 8 * 1024 + 8 * jd + c2) = s1v;
        }
    }
}

extern "C" void kernel_launch(void* const* d_in, const int* in_sizes, int n_in,
                              void* d_out, int out_size) {
    const float* mem  = (const float*)d_in[0];   // [8,1024,2048]
    const float* qry  = (const float*)d_in[1];   // [8,1024,1024]
    const float* bias = (const float*)d_in[2];   // [1024]
    const int*   sl   = (const int*)d_in[3];     // [8,1]
    float* out = (float*)d_out;

    dim3 cgrid(16, 16, 8);
    convert_kv<<<cgrid, 128>>>(mem, sl);

    cudaFuncSetAttribute(attn_mma_kernel, cudaFuncAttributeMaxDynamicSharedMemorySize, SMEM_TOTAL);
    dim3 grid(S_LEN / BQ, 16, 8);
    attn_mma_kernel<<<grid, THREADS, SMEM_TOTAL>>>(mem, qry, bias, sl, out);
}

// round 12
// speedup vs baseline: 1.3165x; 1.3165x over previous
#include <cuda_runtime.h>
#include <cuda_fp16.h>
#include <cstdint>

// R12: two-kernel flash attention; BK=128 tiles + single barrier per tile
// (per-tile fixed-overhead halved -- R11 showed the kernel is overhead-bound,
// not MMA-bound). Single-term fp16 K and V. K1 converts K,V once per
// (b,h,128-key tile) into swizzled device scratch. K2: cp.async double
// buffer, 4 warps x 32 q-rows, Q overlay in BUF1, exp2 softmax with mask
// folded into bias, mean(V) for L==0.

#define S_LEN 1024
#define BQ 128
#define BK 128
#define THREADS 128
#define LOG2E 1.44269504f
#define C2 13.0f

// smem (68KB): BUF0 [0,32K), BUF1 [32K,64K), bias [64K,68K)
#define BUF0    0u
#define BUF1    32768u
#define OFF_Q   32768u
#define KHI     0u
#define VHI     16384u
#define OFF_BIAS 65536u
#define SMEM_TOTAL 69632

#define TILE_BYTES 32768
// [b][h][t] -> 32KB tile: [K 16K][V 16K], swizzled like smem (t: 128-key tiles)
__device__ __align__(16) unsigned char g_kv[8 * 16 * 8 * TILE_BYTES];

static __device__ __forceinline__ uint32_t smem_u32(const void* p) {
    uint32_t a;
    asm("{ .reg .u64 t; cvta.to.shared.u64 t, %1; cvt.u32.u64 %0, t; }" : "=r"(a) : "l"(p));
    return a;
}
static __device__ __forceinline__ void ldsm4(uint32_t addr, uint32_t& r0, uint32_t& r1,
                                             uint32_t& r2, uint32_t& r3) {
    asm volatile("ldmatrix.sync.aligned.m8n8.x4.shared.b16 {%0,%1,%2,%3}, [%4];"
                 : "=r"(r0), "=r"(r1), "=r"(r2), "=r"(r3) : "r"(addr));
}
static __device__ __forceinline__ void ldsm4t(uint32_t addr, uint32_t& r0, uint32_t& r1,
                                              uint32_t& r2, uint32_t& r3) {
    asm volatile("ldmatrix.sync.aligned.m8n8.x4.trans.shared.b16 {%0,%1,%2,%3}, [%4];"
                 : "=r"(r0), "=r"(r1), "=r"(r2), "=r"(r3) : "r"(addr));
}
static __device__ __forceinline__ void mma16816(float* c, uint32_t a0, uint32_t a1,
                                                uint32_t a2, uint32_t a3,
                                                uint32_t b0, uint32_t b1) {
    asm volatile("mma.sync.aligned.m16n8k16.row.col.f32.f16.f16.f32 "
                 "{%0,%1,%2,%3}, {%4,%5,%6,%7}, {%8,%9}, {%0,%1,%2,%3};"
                 : "+f"(c[0]), "+f"(c[1]), "+f"(c[2]), "+f"(c[3])
                 : "r"(a0), "r"(a1), "r"(a2), "r"(a3), "r"(b0), "r"(b1));
}
static __device__ __forceinline__ uint32_t pack_f16(float x, float y) {
    uint32_t r;
    asm("cvt.rn.f16x2.f32 %0, %1, %2;" : "=r"(r) : "f"(y), "f"(x));  // x->lo, y->hi
    return r;
}
static __device__ __forceinline__ void cp16(uint32_t daddr, const void* gaddr) {
    asm volatile("cp.async.cg.shared.global [%0], [%1], 16;" :: "r"(daddr), "l"(gaddr));
}
static __device__ __forceinline__ void cp_commit() {
    asm volatile("cp.async.commit_group;");
}
template <int N> static __device__ __forceinline__ void cp_wait() {
    asm volatile("cp.async.wait_group %0;" :: "n"(N) : "memory");
}

// ---------------- kernel 1: convert K/V to fp16 tiles (128 keys) ----------------
__global__ void __launch_bounds__(128)
convert_kv(const float* __restrict__ mem, const int* __restrict__ seqlen)
{
    const int t = blockIdx.x, h = blockIdx.y, b = blockIdx.z;
    const int L = seqlen[b];
    if (L == 0 || t * BK >= L) return;
    const int tid = threadIdx.x;

    const float* kb = mem + (size_t)b * S_LEN * 2048 + h * 64;
    const float* vb = kb + 1024;
    unsigned char* dst = g_kv + ((size_t)((b * 16 + h) * 8 + t)) * TILE_BYTES;

    #pragma unroll
    for (int i = 0; i < 16; i++) {
        int idx = tid + i * 128, row = idx >> 4, c4 = idx & 15;   // row: key 0..127
        uint32_t off = (uint32_t)(row * 128 + (((c4 >> 1) ^ (row & 7)) << 4) + ((c4 & 1) << 3));
        float4 kv = *reinterpret_cast<const float4*>(kb + (size_t)(t * BK + row) * 2048 + c4 * 4);
        uint2 hk = { pack_f16(kv.x, kv.y), pack_f16(kv.z, kv.w) };
        *reinterpret_cast<uint2*>(dst + KHI + off) = hk;
        float4 vv = *reinterpret_cast<const float4*>(vb + (size_t)(t * BK + row) * 2048 + c4 * 4);
        uint2 hv = { pack_f16(vv.x, vv.y), pack_f16(vv.z, vv.w) };
        *reinterpret_cast<uint2*>(dst + VHI + off) = hv;
    }
}

// ---------------- kernel 2: attention ----------------
__global__ void __launch_bounds__(THREADS, 3)
attn_mma_kernel(const float* __restrict__ mem, const float* __restrict__ qry,
                const float* __restrict__ bias, const int* __restrict__ seqlen,
                float* __restrict__ out)
{
    extern __shared__ char smem[];
    const uint32_t sb = smem_u32(smem);
    const int tid = threadIdx.x, lane = tid & 31, wid = tid >> 5;   // 4 warps
    const int qt = blockIdx.x, h = blockIdx.y, b = blockIdx.z;

    const int L = seqlen[b];
    float* obase0 = out + ((size_t)(b * S_LEN + qt * BQ)) * 1024 + h * 64;

    if (L == 0) {
        // softmax exactly uniform (fp32 rounding of -1e12): O = mean_k V
        const float* vbase = mem + (size_t)b * S_LEN * 2048 + 1024 + h * 64;
        float* red = reinterpret_cast<float*>(smem);
        int d = tid & 63, slc = tid >> 6;
        float s = 0.f;
        #pragma unroll 4
        for (int k = slc * 512; k < slc * 512 + 512; k++)
            s += vbase[(size_t)k * 2048 + d];
        red[slc * 64 + d] = s;
        __syncthreads();
        if (tid < 64) red[128 + tid] = (red[tid] + red[64 + tid]) * (1.f / 1024.f);
        __syncthreads();
        #pragma unroll
        for (int r = 0; r < 16; r++) {
            int idx = tid + r * THREADS;
            int row = idx >> 4, c4 = idx & 15;
            float4 vv = *reinterpret_cast<const float4*>(&red[128 + c4 * 4]);
            *reinterpret_cast<float4*>(obase0 + (size_t)row * 1024 + c4 * 4) = vv;
        }
        return;
    }

    const int nt = (L + BK - 1) >> 7;
    const unsigned char* kvbase = g_kv + ((size_t)((b * 16 + h) * 8)) * TILE_BYTES;

    // prologue: issue tile-0 into BUF0 (Q staging lives in BUF1)
    {
        #pragma unroll
        for (int i = 0; i < 16; i++) {
            int c = tid + i * THREADS;
            cp16(sb + BUF0 + (uint32_t)c * 16, kvbase + (size_t)c * 16);
        }
        cp_commit();
    }

    float* Bs = reinterpret_cast<float*>(smem + OFF_BIAS);
    #pragma unroll
    for (int i = tid; i < S_LEN; i += THREADS)
        Bs[i] = (i < L) ? bias[i] * LOG2E - C2 : -1e30f;

    // Q tile [128 x 64] scaled by (1/8)*log2e, fp16, swizzled -> overlay in BUF1
    const float* qbase = qry + ((size_t)(b * S_LEN + qt * BQ)) * 1024 + h * 64;
    #pragma unroll
    for (int r = 0; r < 16; r++) {
        int idx = tid + r * THREADS;
        int row = idx >> 4, c4 = idx & 15;
        float4 v = *reinterpret_cast<const float4*>(qbase + (size_t)row * 1024 + c4 * 4);
        const float sc = 0.125f * LOG2E;
        uint32_t off = (uint32_t)(row * 128 + (((c4 >> 1) ^ (row & 7)) << 4) + ((c4 & 1) << 3));
        uint2 q16 = { pack_f16(v.x * sc, v.y * sc), pack_f16(v.z * sc, v.w * sc) };
        *reinterpret_cast<uint2*>(smem + OFF_Q + off) = q16;
    }
    __syncthreads();   // Q visible to all warps

    // lane geometry
    const int s7 = lane & 7;
    const int qA = (lane & 7) + ((lane >> 3) & 1) * 8;
    const int qB = lane >> 4;
    const int kA = (lane & 7) + (lane >> 4) * 8;
    const int kB = (lane >> 3) & 1;

    // hoist Q fragments (Q smem dead afterwards; BUF1 refilled only after
    // the loop's first barrier, which is after this hoist completes)
    uint32_t qf[4][2][4];
    #pragma unroll
    for (int kk = 0; kk < 4; kk++)
        #pragma unroll
        for (int rb = 0; rb < 2; rb++)
            ldsm4(sb + OFF_Q + (uint32_t)((32 * wid + 16 * rb + qA) * 128 +
                  (((2 * kk + qB) ^ s7) << 4)),
                  qf[kk][rb][0], qf[kk][rb][1], qf[kk][rb][2], qf[kk][rb][3]);
    __syncthreads();

    float oacc[2][8][4];
    #pragma unroll
    for (int rb = 0; rb < 2; rb++)
        #pragma unroll
        for (int i = 0; i < 8; i++)
            #pragma unroll
            for (int j = 0; j < 4; j++) oacc[rb][i][j] = 0.f;
    float lsA[2] = {0.f, 0.f}, lsB[2] = {0.f, 0.f};

    for (int t = 0; t < nt; t++) {
        const int s0 = t * BK;
        const uint32_t kb = sb + ((t & 1) ? BUF1 : BUF0);

        cp_wait<0>();      // tile t landed
        __syncthreads();   // visible to all warps; all done with the other buffer

        if (t + 1 < nt) {  // refill the other buffer; lands during this compute
            const unsigned char* src = kvbase + (size_t)(t + 1) * TILE_BYTES;
            const uint32_t db = ((t + 1) & 1) ? BUF1 : BUF0;
            #pragma unroll
            for (int i = 0; i < 16; i++) {
                int c = tid + i * THREADS;
                cp16(sb + db + (uint32_t)c * 16, src + (size_t)c * 16);
            }
            cp_commit();
        }

        #pragma unroll
        for (int jj = 0; jj < 8; jj++) {          // 16-key group (8 per 128-key tile)
            float sacc[2][2][4];
            #pragma unroll
            for (int rb = 0; rb < 2; rb++)
                #pragma unroll
                for (int u = 0; u < 2; u++)
                    #pragma unroll
                    for (int j = 0; j < 4; j++) sacc[rb][u][j] = 0.f;

            // ---- S = Q * K (single fp16 term) ----
            #pragma unroll
            for (int kk = 0; kk < 4; kk++) {
                uint32_t kh0, kh1, kh2, kh3;
                uint32_t ak = kb + KHI + (uint32_t)((16 * jj + kA) * 128 +
                              (((2 * kk + kB) ^ s7) << 4));
                ldsm4(ak, kh0, kh1, kh2, kh3);
                #pragma unroll
                for (int rb = 0; rb < 2; rb++) {
                    mma16816(sacc[rb][0], qf[kk][rb][0], qf[kk][rb][1], qf[kk][rb][2], qf[kk][rb][3], kh0, kh1);
                    mma16816(sacc[rb][1], qf[kk][rb][0], qf[kk][rb][1], qf[kk][rb][2], qf[kk][rb][3], kh2, kh3);
                }
            }

            uint32_t pa[2][4];
            #pragma unroll
            for (int u = 0; u < 2; u++) {
                int keyb = s0 + 16 * jj + 8 * u + 2 * (lane & 3);
                float2 bb = *reinterpret_cast<const float2*>(&Bs[keyb]);
                #pragma unroll
                for (int rb = 0; rb < 2; rb++) {
                    float p0 = exp2f(sacc[rb][u][0] + bb.x);
                    float p1 = exp2f(sacc[rb][u][1] + bb.y);
                    float p2 = exp2f(sacc[rb][u][2] + bb.x);
                    float p3 = exp2f(sacc[rb][u][3] + bb.y);
                    lsA[rb] += p0 + p1;
                    lsB[rb] += p2 + p3;
                    pa[rb][2 * u]     = pack_f16(p0, p1);
                    pa[rb][2 * u + 1] = pack_f16(p2, p3);
                }
            }

            // ---- O += P * V ----
            #pragma unroll
            for (int jn = 0; jn < 4; jn++) {
                uint32_t vh0, vh1, vh2, vh3;
                uint32_t av = kb + VHI + (uint32_t)((16 * jj + qA) * 128 +
                              (((2 * jn + qB) ^ s7) << 4));
                ldsm4t(av, vh0, vh1, vh2, vh3);
                #pragma unroll
                for (int rb = 0; rb < 2; rb++) {
                    mma16816(oacc[rb][2 * jn],     pa[rb][0], pa[rb][1], pa[rb][2], pa[rb][3], vh0, vh1);
                    mma16816(oacc[rb][2 * jn + 1], pa[rb][0], pa[rb][1], pa[rb][2], pa[rb][3], vh2, vh3);
                }
            }
        }
        // no second barrier: next iteration's wait+barrier protects the refill
    }

    // normalize within quads, store (each warp: rows 32*wid .. +31)
    #pragma unroll
    for (int rb = 0; rb < 2; rb++) {
        float a = lsA[rb], c = lsB[rb];
        a += __shfl_xor_sync(0xffffffffu, a, 1);
        a += __shfl_xor_sync(0xffffffffu, a, 2);
        c += __shfl_xor_sync(0xffffffffu, c, 1);
        c += __shfl_xor_sync(0xffffffffu, c, 2);
        float invA = 1.f / a, invB = 1.f / c;
        const int r = lane >> 2, c2 = (lane & 3) * 2;
        float* ob = obase0 + (size_t)(32 * wid + 16 * rb + r) * 1024;
        #pragma unroll
        for (int jd = 0; jd < 8; jd++) {
            float2 s0v = { oacc[rb][jd][0] * invA, oacc[rb][jd][1] * invA };
            float2 s1v = { oacc[rb][jd][2] * invB, oacc[rb][jd][3] * invB };
            *reinterpret_cast<float2*>(ob + 8 * jd + c2) = s0v;
            *reinterpret_cast<float2*>(ob + 8 * 1024 + 8 * jd + c2) = s1v;
        }
    }
}

extern "C" void kernel_launch(void* const* d_in, const int* in_sizes, int n_in,
                              void* d_out, int out_size) {
    const float* mem  = (const float*)d_in[0];   // [8,1024,2048]
    const float* qry  = (const float*)d_in[1];   // [8,1024,1024]
    const float* bias = (const float*)d_in[2];   // [1024]
    const int*   sl   = (const int*)d_in[3];     // [8,1]
    float* out = (float*)d_out;

    dim3 cgrid(8, 16, 8);
    convert_kv<<<cgrid, 128>>>(mem, sl);

    cudaFuncSetAttribute(attn_mma_kernel, cudaFuncAttributeMaxDynamicSharedMemorySize, SMEM_TOTAL);
    dim3 grid(S_LEN / BQ, 16, 8);
    attn_mma_kernel<<<grid, THREADS, SMEM_TOTAL>>>(mem, qry, bias, sl, out);
}